// round 1
// baseline (speedup 1.0000x reference)
#include <cuda_runtime.h>
#include <math.h>

#define NBk 4
#define Bb  8
#define Tt  1024
#define Dd  1024
#define Vv  256
#define Ii  2816
#define NN  (Bb*Tt)      // 8192 tokens
#define EPSf 1e-6f

// ---------------- scratch (device globals; no allocation allowed) ------------
__device__ float g_Y [NN*Dd];
__device__ float g_ZF[NN*Dd];
__device__ float g_ZC[NN*Dd];
__device__ float g_ZG[NN*Dd];
__device__ float g_H [NN*Dd];
__device__ float g_S [NN*Dd];
__device__ float g_XO[NN*Dd];
__device__ float g_UU[(size_t)NN*2*Ii];
__device__ float g_GP[(size_t)NN*Ii];
__device__ float g_rA[NN];
__device__ float g_rB[NN];
__device__ float g_LB[NBk*Dd];

// ---------------- small helpers ----------------------------------------------
__device__ __forceinline__ float sigm(float x) { return 1.f / (1.f + expf(-x)); }

__device__ __forceinline__ void blockReduce2(float& s1, float& s2) {
    __shared__ float r1[256], r2[256];
    int t = threadIdx.x;
    r1[t] = s1; r2[t] = s2; __syncthreads();
    for (int s = 128; s > 0; s >>= 1) {
        if (t < s) { r1[t] += r1[t+s]; r2[t] += r2[t+s]; }
        __syncthreads();
    }
    s1 = r1[0]; s2 = r2[0];
}

// ---------------- lb = cumsum(softmax(weight_l)) - weight_l[:, :1] -----------
__global__ void lb_kernel(const float* __restrict__ wl) {
    __shared__ float sm[Dd];
    __shared__ float red[256];
    int i = blockIdx.x;
    const float* w = wl + i * Dd;
    int t = threadIdx.x;
    float mx = -1e30f;
    for (int d = t; d < Dd; d += 256) mx = fmaxf(mx, w[d]);
    red[t] = mx; __syncthreads();
    for (int s = 128; s > 0; s >>= 1) { if (t < s) red[t] = fmaxf(red[t], red[t+s]); __syncthreads(); }
    mx = red[0]; __syncthreads();
    float sum = 0.f;
    for (int d = t; d < Dd; d += 256) { float e = expf(w[d] - mx); sm[d] = e; sum += e; }
    red[t] = sum; __syncthreads();
    for (int s = 128; s > 0; s >>= 1) { if (t < s) red[t] += red[t+s]; __syncthreads(); }
    float Z = red[0];
    float w0 = w[0];
    __syncthreads();
    for (int d = t; d < Dd; d += 256) {
        float c = 0.f;
        for (int k = 0; k <= d; k++) c += sm[k];
        g_LB[i * Dd + d] = c / Z - w0;
    }
}

// ---------------- y = emb[x] --------------------------------------------------
__global__ void embed_kernel(const int* __restrict__ x, const float* __restrict__ emb) {
    int idx = blockIdx.x * blockDim.x + threadIdx.x;      // over NN*Dd/4
    int n  = idx / (Dd/4);
    int d4 = idx % (Dd/4);
    int b = n / Tt, t = n % Tt;
    int tok = x[b * Tt + t];
    ((float4*)g_Y)[(size_t)n * (Dd/4) + d4] = ((const float4*)(emb + (size_t)tok * Dd))[d4];
}

// ---------------- row rms stats ----------------------------------------------
// w == null : out[n] = rsqrt(mean(x^2)+eps)
// w != null : r1 = rsqrt(mean(x^2)+eps); r2 = rsqrt(r1^2*mean((x*w)^2)+eps); out = r1*r2
// (this is exactly the combined scale for rms(rms(x, implicit-w1-chain)) paths)
__global__ void rms_rows_kernel(const float* __restrict__ X, const float* __restrict__ w,
                                float* __restrict__ out, int D) {
    int n = blockIdx.x;
    const float* x = X + (size_t)n * D;
    float s1 = 0.f, s2 = 0.f;
    for (int d = threadIdx.x; d < D; d += 256) {
        float v = x[d];
        s1 += v * v;
        if (w) { float vw = v * w[d]; s2 += vw * vw; }
    }
    blockReduce2(s1, s2);
    if (threadIdx.x == 0) {
        float r1 = rsqrtf(s1 / D + EPSf);
        if (w) { float r2 = rsqrtf(r1 * r1 * s2 / D + EPSf); out[n] = r1 * r2; }
        else   out[n] = r1;
    }
}

// ---------------- gated linear recurrence over t -----------------------------
__global__ void scan_kernel(const float* __restrict__ ZF, const float* __restrict__ ZC,
                            const float* __restrict__ lbrow, float* __restrict__ H) {
    int id = blockIdx.x * blockDim.x + threadIdx.x;  // B*D
    int b = id / Dd, d = id % Dd;
    float l = lbrow[d];
    float h = 0.f;
    const float* zf = ZF + (size_t)b * Tt * Dd + d;
    const float* zc = ZC + (size_t)b * Tt * Dd + d;
    float*       hp = H  + (size_t)b * Tt * Dd + d;
    #pragma unroll 4
    for (int t = 0; t < Tt; t++) {
        float f  = l + (1.f - l) * sigm(zf[(size_t)t * Dd]);
        float zv = zc[(size_t)t * Dd];
        float c  = zv * sigm(zv);
        h = f * h + (1.f - f) * c;
        hp[(size_t)t * Dd] = h;
    }
}

// ---------------- s = x_g * h * sigmoid(h), plus its row rms -----------------
__global__ void s_kernel(const float* __restrict__ ZG, const float* __restrict__ rz,
                         const float* __restrict__ wnorm, const float* __restrict__ H,
                         float* __restrict__ S, float* __restrict__ rs_out) {
    int n = blockIdx.x;
    float r = rz[n];
    float s2 = 0.f, dummy = 0.f;
    for (int d = threadIdx.x; d < Dd; d += 256) {
        size_t o = (size_t)n * Dd + d;
        float xg = ZG[o] * r * wnorm[d];
        float h  = H[o];
        float s  = xg * h * sigm(h);
        S[o] = s;
        s2 += s * s;
    }
    blockReduce2(s2, dummy);
    if (threadIdx.x == 0) rs_out[n] = rsqrtf(s2 / Dd + EPSf);
}

// ---------------- GLU gate: gp = silu(uu[:I]) * uu[I:], plus row rms ---------
__global__ void glu_kernel(const float* __restrict__ UU, float* __restrict__ GP,
                           float* __restrict__ rg) {
    int n = blockIdx.x;
    const float* u = UU + (size_t)n * 2 * Ii;
    float s2 = 0.f, dummy = 0.f;
    for (int k = threadIdx.x; k < Ii; k += 256) {
        float a = u[k], b = u[Ii + k];
        float g = a * sigm(a) * b;
        GP[(size_t)n * Ii + k] = g;
        s2 += g * g;
    }
    blockReduce2(s2, dummy);
    if (threadIdx.x == 0) rg[n] = rsqrtf(s2 / Ii + EPSf);
}

// ---------------- fused SGEMM: C = (rs[n]*cs1[k]*cs2[k]*A) @ W^T + bias + addC
// A [N,K] rm, W [M,K] rm.  N,M mult of 128; K mult of 8.
__global__ __launch_bounds__(256, 2)
void sgemm_nt(int N, int M, int K,
              const float* __restrict__ A,
              const float* __restrict__ rowscale,
              const float* __restrict__ cs1,
              const float* __restrict__ cs2,
              const float* __restrict__ W,
              const float* __restrict__ bias,
              const float* __restrict__ addC,
              float* __restrict__ C)
{
    __shared__ float As[8][128];
    __shared__ float Ws[8][128];

    const int t   = threadIdx.x;
    const int row = t >> 1;
    const int kq  = (t & 1) << 2;
    const int bx  = blockIdx.x;
    const int by  = blockIdx.y;

    const float* Ag = A + (size_t)(by * 128 + row) * K + kq;
    const float* Wg = W + (size_t)(bx * 128 + row) * K + kq;
    const float rs  = rowscale ? rowscale[by * 128 + row] : 1.0f;

    const int ty = t >> 4;
    const int tx = t & 15;

    float acc[8][8];
    #pragma unroll
    for (int i = 0; i < 8; i++)
        #pragma unroll
        for (int j = 0; j < 8; j++) acc[i][j] = 0.f;

    const int ktiles = K >> 3;
    float4 a = *(const float4*)Ag;
    float4 w = *(const float4*)Wg;
    float4 cv = make_float4(1.f, 1.f, 1.f, 1.f);
    if (cs1) cv = *(const float4*)(cs1 + kq);
    if (cs2) { float4 c2 = *(const float4*)(cs2 + kq);
               cv.x *= c2.x; cv.y *= c2.y; cv.z *= c2.z; cv.w *= c2.w; }

    for (int kt = 0; kt < ktiles; kt++) {
        As[kq+0][row] = a.x * rs * cv.x;
        As[kq+1][row] = a.y * rs * cv.y;
        As[kq+2][row] = a.z * rs * cv.z;
        As[kq+3][row] = a.w * rs * cv.w;
        Ws[kq+0][row] = w.x;
        Ws[kq+1][row] = w.y;
        Ws[kq+2][row] = w.z;
        Ws[kq+3][row] = w.w;
        __syncthreads();

        if (kt + 1 < ktiles) {
            int off = (kt + 1) << 3;
            a = *(const float4*)(Ag + off);
            w = *(const float4*)(Wg + off);
            cv = make_float4(1.f, 1.f, 1.f, 1.f);
            if (cs1) cv = *(const float4*)(cs1 + off + kq);
            if (cs2) { float4 c2 = *(const float4*)(cs2 + off + kq);
                       cv.x *= c2.x; cv.y *= c2.y; cv.z *= c2.z; cv.w *= c2.w; }
        }

        #pragma unroll
        for (int kk = 0; kk < 8; kk++) {
            float4 a0 = *(const float4*)&As[kk][ty * 8];
            float4 a1 = *(const float4*)&As[kk][ty * 8 + 4];
            float4 w0 = *(const float4*)&Ws[kk][tx * 8];
            float4 w1 = *(const float4*)&Ws[kk][tx * 8 + 4];
            float af[8] = {a0.x, a0.y, a0.z, a0.w, a1.x, a1.y, a1.z, a1.w};
            float wf[8] = {w0.x, w0.y, w0.z, w0.w, w1.x, w1.y, w1.z, w1.w};
            #pragma unroll
            for (int i = 0; i < 8; i++)
                #pragma unroll
                for (int j = 0; j < 8; j++)
                    acc[i][j] = fmaf(af[i], wf[j], acc[i][j]);
        }
        __syncthreads();
    }

    float bf[8];
    #pragma unroll
    for (int j = 0; j < 8; j++)
        bf[j] = bias ? bias[bx * 128 + tx * 8 + j] : 0.f;

    #pragma unroll
    for (int i = 0; i < 8; i++) {
        size_t n = (size_t)(by * 128 + ty * 8 + i);
        size_t base = n * M + bx * 128 + tx * 8;
        #pragma unroll
        for (int jq = 0; jq < 8; jq += 4) {
            float4 v;
            v.x = acc[i][jq+0] + bf[jq+0];
            v.y = acc[i][jq+1] + bf[jq+1];
            v.z = acc[i][jq+2] + bf[jq+2];
            v.w = acc[i][jq+3] + bf[jq+3];
            if (addC) {
                float4 ad = *(const float4*)(addC + base + jq);
                v.x += ad.x; v.y += ad.y; v.z += ad.z; v.w += ad.w;
            }
            *(float4*)(C + base + jq) = v;
        }
    }
}

// ---------------- launcher ----------------------------------------------------
extern "C" void kernel_launch(void* const* d_in, const int* in_sizes, int n_in,
                              void* d_out, int out_size) {
    const int*   x       = (const int*)  d_in[0];
    const float* emb     = (const float*)d_in[1];
    const float* wg_in   = (const float*)d_in[2];
    const float* wg_f    = (const float*)d_in[3];
    const float* wg_c    = (const float*)d_in[4];
    const float* wg_g    = (const float*)d_in[5];
    const float* wg_norm = (const float*)d_in[6];
    const float* lf_w    = (const float*)d_in[7];
    const float* lf_b    = (const float*)d_in[8];
    const float* lc_w    = (const float*)d_in[9];
    const float* lc_b    = (const float*)d_in[10];
    const float* lg_w    = (const float*)d_in[11];
    const float* lg_b    = (const float*)d_in[12];
    const float* weight_l= (const float*)d_in[13];
    const float* wg_o    = (const float*)d_in[14];
    const float* lo_w    = (const float*)d_in[15];
    const float* lo_b    = (const float*)d_in[16];
    const float* glu_wg  = (const float*)d_in[17];
    const float* glu_wgo = (const float*)d_in[18];
    const float* glu_wd  = (const float*)d_in[19];
    const float* lu_w    = (const float*)d_in[20];
    const float* lu_b    = (const float*)d_in[21];
    const float* ln_w    = (const float*)d_in[22];
    const float* ln_b    = (const float*)d_in[23];
    const float* out_w   = (const float*)d_in[24];
    const float* out_b   = (const float*)d_in[25];
    float* out = (float*)d_out;

    float *pY, *pZF, *pZC, *pZG, *pH, *pS, *pXO, *pUU, *pGP, *prA, *prB, *pLB;
    cudaGetSymbolAddress((void**)&pY,  g_Y);
    cudaGetSymbolAddress((void**)&pZF, g_ZF);
    cudaGetSymbolAddress((void**)&pZC, g_ZC);
    cudaGetSymbolAddress((void**)&pZG, g_ZG);
    cudaGetSymbolAddress((void**)&pH,  g_H);
    cudaGetSymbolAddress((void**)&pS,  g_S);
    cudaGetSymbolAddress((void**)&pXO, g_XO);
    cudaGetSymbolAddress((void**)&pUU, g_UU);
    cudaGetSymbolAddress((void**)&pGP, g_GP);
    cudaGetSymbolAddress((void**)&prA, g_rA);
    cudaGetSymbolAddress((void**)&prB, g_rB);
    cudaGetSymbolAddress((void**)&pLB, g_LB);

    lb_kernel<<<NBk, 256>>>(weight_l);
    embed_kernel<<<(NN * Dd / 4) / 256, 256>>>(x, emb);

    dim3 gD(Dd / 128, NN / 128);      // D-wide GEMMs
    dim3 gU(2 * Ii / 128, NN / 128);  // up-proj
    dim3 gV(Vv / 128, NN / 128);      // logits

    for (int i = 0; i < NBk; i++) {
        const float* wgin = wg_in   + i * Dd;
        const float* wgf  = wg_f    + i * Dd;
        const float* wgc  = wg_c    + i * Dd;
        const float* wgg  = wg_g    + i * Dd;
        const float* wgn  = wg_norm + i * Dd;
        const float* wgo  = wg_o    + i * Dd;
        const float* gwg  = glu_wg  + i * Dd;
        const float* gwgo = glu_wgo + i * Dd;
        const float* gwd  = glu_wd  + i * Ii;

        // combined scale for rms(rms(y, wg_in)) chain
        rms_rows_kernel<<<NN, 256>>>(pY, wgin, prA, Dd);

        // f/c/g projections (rms folded in as row*col scales)
        sgemm_nt<<<gD, 256>>>(NN, Dd, Dd, pY, prA, wgin, wgf,
                              lf_w + (size_t)i * Dd * Dd, lf_b + i * Dd, nullptr, pZF);
        sgemm_nt<<<gD, 256>>>(NN, Dd, Dd, pY, prA, wgin, wgc,
                              lc_w + (size_t)i * Dd * Dd, lc_b + i * Dd, nullptr, pZC);
        sgemm_nt<<<gD, 256>>>(NN, Dd, Dd, pY, prA, wgin, wgg,
                              lg_w + (size_t)i * Dd * Dd, lg_b + i * Dd, nullptr, pZG);

        // gated recurrence over t (elementwise in (b,d))
        scan_kernel<<<(Bb * Dd) / 128, 128>>>(pZF, pZC, pLB + i * Dd, pH);

        // x_g = rms(zg, wg_norm); s = x_g * h * sigmoid(h); its row rms
        rms_rows_kernel<<<NN, 256>>>(pZG, nullptr, prB, Dd);
        s_kernel<<<NN, 256>>>(pZG, prB, wgn, pH, pS, prB);

        // x_o = y + rms(s, wg_o_out) @ lo_w^T + lo_b
        sgemm_nt<<<gD, 256>>>(NN, Dd, Dd, pS, prB, wgo, nullptr,
                              lo_w + (size_t)i * Dd * Dd, lo_b + i * Dd, pY, pXO);

        // GLU: combined scale for rms(rms(x_o, glu_wg), glu_wgo)
        rms_rows_kernel<<<NN, 256>>>(pXO, gwg, prA, Dd);
        sgemm_nt<<<gU, 256>>>(NN, 2 * Ii, Dd, pXO, prA, gwg, gwgo,
                              lu_w + (size_t)i * 2 * Ii * Dd, lu_b + (size_t)i * 2 * Ii,
                              nullptr, pUU);
        glu_kernel<<<NN, 256>>>(pUU, pGP, prB);

        // y_next = x_o + rms(gp, glu_wd) @ ln_w^T + ln_b
        sgemm_nt<<<gD, 256>>>(NN, Dd, Ii, pGP, prB, gwd, nullptr,
                              ln_w + (size_t)i * Dd * Ii, ln_b + i * Dd, pXO, pY);
    }

    // logits = y @ out_w^T + out_b  -> [B,T,V] directly (n = b*T+t)
    sgemm_nt<<<gV, 256>>>(NN, Vv, Dd, pY, nullptr, nullptr, nullptr,
                          out_w, out_b, nullptr, out);
}

// round 4
// speedup vs baseline: 3.8450x; 3.8450x over previous
#include <cuda_runtime.h>
#include <cstdint>
#include <math.h>

#define NBk 4
#define Bb  8
#define Tt  1024
#define Dd  1024
#define Vv  256
#define Ii  2816
#define NN  (Bb*Tt)      // 8192 tokens
#define EPSf 1e-6f
#define TC  128          // scan chunk length
#define CH  (Tt/TC)      // 8 chunks

// ---------------- scratch (device globals; no allocation allowed) ------------
__device__ float g_Y [NN*Dd];
__device__ float g_ZF[NN*Dd];
__device__ float g_ZC[NN*Dd];
__device__ float g_ZG[NN*Dd];
__device__ float g_H [NN*Dd];
__device__ float g_S [NN*Dd];
__device__ float g_XO[NN*Dd];
__device__ float g_UU[(size_t)NN*2*Ii];
__device__ float g_GP[(size_t)NN*Ii];
__device__ float g_WS[(size_t)2*Ii*Dd];   // scaled-weight scratch (max 2I x D)
__device__ float g_rA[NN];
__device__ float g_rB[NN];
__device__ float g_LB[NBk*Dd];
__device__ float g_SA[Bb*CH*Dd];
__device__ float g_SB[Bb*CH*Dd];

// ---------------- PTX helpers -------------------------------------------------
__device__ __forceinline__ uint32_t smem_u32(const void* p) {
    uint32_t a;
    asm("{ .reg .u64 t; cvta.to.shared.u64 t, %1; cvt.u32.u64 %0, t; }" : "=r"(a) : "l"(p));
    return a;
}
static __device__ __forceinline__ void cp16(uint32_t saddr, const void* gaddr) {
    asm volatile("cp.async.cg.shared.global [%0], [%1], 16;" :: "r"(saddr), "l"(gaddr));
}
static __device__ __forceinline__ void cp_commit() {
    asm volatile("cp.async.commit_group;" ::: "memory");
}
// ld.shared + round-to-tf32 (RNA)
static __device__ __forceinline__ uint32_t ldcvt(uint32_t addr) {
    uint32_t x;
    asm volatile("ld.shared.b32 %0, [%1];" : "=r"(x) : "r"(addr));
    asm("cvt.rna.tf32.f32 %0, %0;" : "+r"(x));
    return x;
}
static __device__ __forceinline__ void mma_tf32(float* c, uint32_t a0, uint32_t a1,
                                                uint32_t a2, uint32_t a3,
                                                uint32_t b0, uint32_t b1) {
    asm volatile("mma.sync.aligned.m16n8k8.row.col.f32.tf32.tf32.f32 "
        "{%0,%1,%2,%3},{%4,%5,%6,%7},{%8,%9},{%0,%1,%2,%3};"
        : "+f"(c[0]), "+f"(c[1]), "+f"(c[2]), "+f"(c[3])
        : "r"(a0), "r"(a1), "r"(a2), "r"(a3), "r"(b0), "r"(b1));
}

#define GEMM_SMEM_BYTES (1024 + 4*16384)   // align slack + 2 stages x (A16K + B16K)

// ---------------- tensor-core GEMM (mma.sync tf32) ---------------------------
// C[n, m] = rs[n] * sum_k A[n,k]*W[m,k] + bias[m] (+ addC[n,m])
// A [N,K] rm, W [M,K] rm. grid = (M/128, N/128), 256 threads. K mult of 32.
__global__ void __launch_bounds__(256, 2)
tc_gemm(int M, int K,
        const float* __restrict__ A, const float* __restrict__ W,
        const float* __restrict__ rowscale, const float* __restrict__ bias,
        const float* __restrict__ addC, float* __restrict__ C)
{
    extern __shared__ char smem_raw[];
    uint32_t base = (smem_u32(smem_raw) + 1023u) & ~1023u;
    uint32_t Aoff = base;
    uint32_t Boff = base + 2 * 16384;

    const int tid  = threadIdx.x;
    const int wid  = tid >> 5, lane = tid & 31;
    const int g    = lane >> 2, tig = lane & 3;
    const int rowA = blockIdx.y << 7;
    const int colB = blockIdx.x << 7;
    const int KT   = K >> 5;

    const int m_base = (wid >> 2) * 64;   // 0 or 64
    const int n_base = (wid & 3) * 32;    // 0,32,64,96

    // per-subtile row base bytes + swizzle masks (SW128: mask = (row*16)&0x70)
    uint32_t aRB[4][2], aMK[4][2], bRB[4], bMK[4];
    #pragma unroll
    for (int mi = 0; mi < 4; mi++) {
        int r0 = m_base + mi * 16 + g;
        int r1 = r0 + 8;
        aRB[mi][0] = (uint32_t)r0 << 7; aMK[mi][0] = ((uint32_t)r0 << 4) & 0x70u;
        aRB[mi][1] = (uint32_t)r1 << 7; aMK[mi][1] = ((uint32_t)r1 << 4) & 0x70u;
    }
    #pragma unroll
    for (int ni = 0; ni < 4; ni++) {
        int nr = n_base + ni * 8 + g;
        bRB[ni] = (uint32_t)nr << 7; bMK[ni] = ((uint32_t)nr << 4) & 0x70u;
    }

    float acc[4][4][4];
    #pragma unroll
    for (int mi = 0; mi < 4; mi++)
        #pragma unroll
        for (int ni = 0; ni < 4; ni++)
            #pragma unroll
            for (int q = 0; q < 4; q++) acc[mi][ni][q] = 0.f;

    // ---- tile loader: k-chunk kt into stage s (SW128 swizzled) ----
    #define LOAD_CHUNK(kt_, s_) do { \
        uint32_t _sA = Aoff + (s_) * 16384, _sB = Boff + (s_) * 16384; \
        const float* _Ab = A + (size_t)rowA * K + (size_t)(kt_) * 32; \
        const float* _Wb = W + (size_t)colB * K + (size_t)(kt_) * 32; \
        _Pragma("unroll") \
        for (int _i = 0; _i < 4; _i++) { \
            int _idx = tid + _i * 256; \
            int _r = _idx >> 3, _seg = _idx & 7; \
            uint32_t _b = ((uint32_t)_r << 7) + ((uint32_t)_seg << 4); \
            uint32_t _sw = _b ^ ((_b >> 3) & 0x70u); \
            cp16(_sA + _sw, _Ab + (size_t)_r * K + _seg * 4); \
            cp16(_sB + _sw, _Wb + (size_t)_r * K + _seg * 4); \
        } \
        cp_commit(); \
    } while (0)

    LOAD_CHUNK(0, 0);
    if (KT > 1) LOAD_CHUNK(1, 1);

    for (int kt = 0; kt < KT; kt++) {
        const int s = kt & 1;
        if (kt + 1 < KT) asm volatile("cp.async.wait_group 1;" ::: "memory");
        else             asm volatile("cp.async.wait_group 0;" ::: "memory");
        __syncthreads();

        const uint32_t aS = Aoff + s * 16384;
        const uint32_t bS = Boff + s * 16384;
        #pragma unroll
        for (int kk = 0; kk < 4; kk++) {
            const uint32_t c0b = (uint32_t)(kk * 8 + tig) << 2;
            const uint32_t c1b = c0b + 16u;
            uint32_t bf[4][2];
            #pragma unroll
            for (int ni = 0; ni < 4; ni++) {
                bf[ni][0] = ldcvt(bS + bRB[ni] + (c0b ^ bMK[ni]));
                bf[ni][1] = ldcvt(bS + bRB[ni] + (c1b ^ bMK[ni]));
            }
            #pragma unroll
            for (int mi = 0; mi < 4; mi++) {
                uint32_t a0 = ldcvt(aS + aRB[mi][0] + (c0b ^ aMK[mi][0]));
                uint32_t a1 = ldcvt(aS + aRB[mi][1] + (c0b ^ aMK[mi][1]));
                uint32_t a2 = ldcvt(aS + aRB[mi][0] + (c1b ^ aMK[mi][0]));
                uint32_t a3 = ldcvt(aS + aRB[mi][1] + (c1b ^ aMK[mi][1]));
                #pragma unroll
                for (int ni = 0; ni < 4; ni++)
                    mma_tf32(acc[mi][ni], a0, a1, a2, a3, bf[ni][0], bf[ni][1]);
            }
        }
        __syncthreads();
        if (kt + 2 < KT) LOAD_CHUNK(kt + 2, s);
    }

    // ---- epilogue: rowscale, bias, optional residual ----
    #pragma unroll
    for (int mi = 0; mi < 4; mi++) {
        const int row0 = rowA + m_base + mi * 16 + g;
        const int row1 = row0 + 8;
        const float rs0 = rowscale ? rowscale[row0] : 1.0f;
        const float rs1 = rowscale ? rowscale[row1] : 1.0f;
        #pragma unroll
        for (int ni = 0; ni < 4; ni++) {
            const int col = colB + n_base + ni * 8 + 2 * tig;
            float2 bv = *(const float2*)(bias + col);
            size_t o0 = (size_t)row0 * M + col;
            size_t o1 = (size_t)row1 * M + col;
            float2 v0, v1;
            v0.x = acc[mi][ni][0] * rs0 + bv.x;
            v0.y = acc[mi][ni][1] * rs0 + bv.y;
            v1.x = acc[mi][ni][2] * rs1 + bv.x;
            v1.y = acc[mi][ni][3] * rs1 + bv.y;
            if (addC) {
                float2 r0 = *(const float2*)(addC + o0);
                float2 r1 = *(const float2*)(addC + o1);
                v0.x += r0.x; v0.y += r0.y;
                v1.x += r1.x; v1.y += r1.y;
            }
            *(float2*)(C + o0) = v0;
            *(float2*)(C + o1) = v1;
        }
    }
    #undef LOAD_CHUNK
}

// ---------------- weight pre-scale: Wo[m,k] = W[m,k]*c1[k](*c2[k]) -----------
__global__ void wscale_kernel(const float4* __restrict__ W, const float* __restrict__ c1,
                              const float* __restrict__ c2, float4* __restrict__ Wo,
                              int K4, int total4) {
    int i = blockIdx.x * blockDim.x + threadIdx.x;
    if (i >= total4) return;
    int k4 = i % K4;
    float4 w = W[i];
    float4 a = ((const float4*)c1)[k4];
    if (c2) {
        float4 b = ((const float4*)c2)[k4];
        a.x *= b.x; a.y *= b.y; a.z *= b.z; a.w *= b.w;
    }
    w.x *= a.x; w.y *= a.y; w.z *= a.z; w.w *= a.w;
    Wo[i] = w;
}

// ---------------- small helpers ----------------------------------------------
__device__ __forceinline__ float sigm(float x) { return 1.f / (1.f + __expf(-x)); }

__device__ __forceinline__ void blockReduce2(float& s1, float& s2) {
    __shared__ float r1[256], r2[256];
    int t = threadIdx.x;
    r1[t] = s1; r2[t] = s2; __syncthreads();
    for (int s = 128; s > 0; s >>= 1) {
        if (t < s) { r1[t] += r1[t+s]; r2[t] += r2[t+s]; }
        __syncthreads();
    }
    s1 = r1[0]; s2 = r2[0];
}

// ---------------- lb = cumsum(softmax(weight_l)) - weight_l[:, :1] -----------
__global__ void lb_kernel(const float* __restrict__ wl) {
    __shared__ float sm[Dd];
    __shared__ float red[256];
    int i = blockIdx.x;
    const float* w = wl + i * Dd;
    int t = threadIdx.x;
    float mx = -1e30f;
    for (int d = t; d < Dd; d += 256) mx = fmaxf(mx, w[d]);
    red[t] = mx; __syncthreads();
    for (int s = 128; s > 0; s >>= 1) { if (t < s) red[t] = fmaxf(red[t], red[t+s]); __syncthreads(); }
    mx = red[0]; __syncthreads();
    float sum = 0.f;
    for (int d = t; d < Dd; d += 256) { float e = expf(w[d] - mx); sm[d] = e; sum += e; }
    red[t] = sum; __syncthreads();
    for (int s = 128; s > 0; s >>= 1) { if (t < s) red[t] += red[t+s]; __syncthreads(); }
    float Z = red[0];
    float w0 = w[0];
    __syncthreads();
    for (int d = t; d < Dd; d += 256) {
        float c = 0.f;
        for (int k = 0; k <= d; k++) c += sm[k];
        g_LB[i * Dd + d] = c / Z - w0;
    }
}

// ---------------- y = emb[x] --------------------------------------------------
__global__ void embed_kernel(const int* __restrict__ x, const float* __restrict__ emb) {
    int idx = blockIdx.x * blockDim.x + threadIdx.x;
    int n  = idx / (Dd/4);
    int d4 = idx % (Dd/4);
    int b = n / Tt, t = n % Tt;
    int tok = x[b * Tt + t];
    ((float4*)g_Y)[(size_t)n * (Dd/4) + d4] = ((const float4*)(emb + (size_t)tok * Dd))[d4];
}

// ---------------- row rms stats ----------------------------------------------
__global__ void rms_rows_kernel(const float* __restrict__ X, const float* __restrict__ w,
                                float* __restrict__ out, int D) {
    int n = blockIdx.x;
    const float* x = X + (size_t)n * D;
    float s1 = 0.f, s2 = 0.f;
    for (int d = threadIdx.x; d < D; d += 256) {
        float v = x[d];
        s1 += v * v;
        if (w) { float vw = v * w[d]; s2 += vw * vw; }
    }
    blockReduce2(s1, s2);
    if (threadIdx.x == 0) {
        float r1 = rsqrtf(s1 / D + EPSf);
        if (w) { float r2 = rsqrtf(r1 * r1 * s2 / D + EPSf); out[n] = r1 * r2; }
        else   out[n] = r1;
    }
}

// ---------------- chunked linear-recurrence scan ------------------------------
__global__ void scan1_kernel(const float* __restrict__ ZF, const float* __restrict__ ZC,
                             const float* __restrict__ lbrow) {
    int id = blockIdx.x * blockDim.x + threadIdx.x;    // Bb*CH*Dd
    int d = id % Dd;
    int c = (id / Dd) % CH;
    int b = id / (Dd * CH);
    float l = lbrow[d];
    size_t base = ((size_t)b * Tt + (size_t)c * TC) * Dd + d;
    float a = 1.f, h = 0.f;
    for (int t = 0; t < TC; t++) {
        float f  = l + (1.f - l) * sigm(ZF[base + (size_t)t * Dd]);
        float zv = ZC[base + (size_t)t * Dd];
        float cc = zv * sigm(zv);
        h = f * h + (1.f - f) * cc;
        a *= f;
    }
    g_SA[id] = a;
    g_SB[id] = h;
}
__global__ void scan2_kernel(const float* __restrict__ ZF, const float* __restrict__ ZC,
                             const float* __restrict__ lbrow, float* __restrict__ H) {
    int id = blockIdx.x * blockDim.x + threadIdx.x;
    int d = id % Dd;
    int c = (id / Dd) % CH;
    int b = id / (Dd * CH);
    float l = lbrow[d];
    float h = 0.f;
    for (int j = 0; j < c; j++) {
        int sid = (b * CH + j) * Dd + d;
        h = g_SA[sid] * h + g_SB[sid];
    }
    size_t base = ((size_t)b * Tt + (size_t)c * TC) * Dd + d;
    for (int t = 0; t < TC; t++) {
        float f  = l + (1.f - l) * sigm(ZF[base + (size_t)t * Dd]);
        float zv = ZC[base + (size_t)t * Dd];
        float cc = zv * sigm(zv);
        h = f * h + (1.f - f) * cc;
        H[base + (size_t)t * Dd] = h;
    }
}

// ---------------- s = x_g * h * sigmoid(h), plus its row rms -----------------
__global__ void s_kernel(const float* __restrict__ ZG, const float* __restrict__ rz,
                         const float* __restrict__ wnorm, const float* __restrict__ H,
                         float* __restrict__ S, float* __restrict__ rs_out) {
    int n = blockIdx.x;
    float r = rz[n];
    float s2 = 0.f, dummy = 0.f;
    for (int d = threadIdx.x; d < Dd; d += 256) {
        size_t o = (size_t)n * Dd + d;
        float xg = ZG[o] * r * wnorm[d];
        float h  = H[o];
        float s  = xg * h * sigm(h);
        S[o] = s;
        s2 += s * s;
    }
    blockReduce2(s2, dummy);
    if (threadIdx.x == 0) rs_out[n] = rsqrtf(s2 / Dd + EPSf);
}

// ---------------- GLU gate: gp = silu(uu[:I]) * uu[I:], plus row rms ---------
__global__ void glu_kernel(const float* __restrict__ UU, float* __restrict__ GP,
                           float* __restrict__ rg) {
    int n = blockIdx.x;
    const float* u = UU + (size_t)n * 2 * Ii;
    float s2 = 0.f, dummy = 0.f;
    for (int k = threadIdx.x; k < Ii; k += 256) {
        float a = u[k], b = u[Ii + k];
        float g = a * sigm(a) * b;
        GP[(size_t)n * Ii + k] = g;
        s2 += g * g;
    }
    blockReduce2(s2, dummy);
    if (threadIdx.x == 0) rg[n] = rsqrtf(s2 / Ii + EPSf);
}

// ---------------- launcher ----------------------------------------------------
extern "C" void kernel_launch(void* const* d_in, const int* in_sizes, int n_in,
                              void* d_out, int out_size) {
    const int*   x       = (const int*)  d_in[0];
    const float* emb     = (const float*)d_in[1];
    const float* wg_in   = (const float*)d_in[2];
    const float* wg_f    = (const float*)d_in[3];
    const float* wg_c    = (const float*)d_in[4];
    const float* wg_g    = (const float*)d_in[5];
    const float* wg_norm = (const float*)d_in[6];
    const float* lf_w    = (const float*)d_in[7];
    const float* lf_b    = (const float*)d_in[8];
    const float* lc_w    = (const float*)d_in[9];
    const float* lc_b    = (const float*)d_in[10];
    const float* lg_w    = (const float*)d_in[11];
    const float* lg_b    = (const float*)d_in[12];
    const float* weight_l= (const float*)d_in[13];
    const float* wg_o    = (const float*)d_in[14];
    const float* lo_w    = (const float*)d_in[15];
    const float* lo_b    = (const float*)d_in[16];
    const float* glu_wg  = (const float*)d_in[17];
    const float* glu_wgo = (const float*)d_in[18];
    const float* glu_wd  = (const float*)d_in[19];
    const float* lu_w    = (const float*)d_in[20];
    const float* lu_b    = (const float*)d_in[21];
    const float* ln_w    = (const float*)d_in[22];
    const float* ln_b    = (const float*)d_in[23];
    const float* out_w   = (const float*)d_in[24];
    const float* out_b   = (const float*)d_in[25];
    float* out = (float*)d_out;

    float *pY, *pZF, *pZC, *pZG, *pH, *pS, *pXO, *pUU, *pGP, *pWS, *prA, *prB, *pLB;
    cudaGetSymbolAddress((void**)&pY,  g_Y);
    cudaGetSymbolAddress((void**)&pZF, g_ZF);
    cudaGetSymbolAddress((void**)&pZC, g_ZC);
    cudaGetSymbolAddress((void**)&pZG, g_ZG);
    cudaGetSymbolAddress((void**)&pH,  g_H);
    cudaGetSymbolAddress((void**)&pS,  g_S);
    cudaGetSymbolAddress((void**)&pXO, g_XO);
    cudaGetSymbolAddress((void**)&pUU, g_UU);
    cudaGetSymbolAddress((void**)&pGP, g_GP);
    cudaGetSymbolAddress((void**)&pWS, g_WS);
    cudaGetSymbolAddress((void**)&prA, g_rA);
    cudaGetSymbolAddress((void**)&prB, g_rB);
    cudaGetSymbolAddress((void**)&pLB, g_LB);

    cudaFuncSetAttribute(tc_gemm, cudaFuncAttributeMaxDynamicSharedMemorySize, GEMM_SMEM_BYTES);

    lb_kernel<<<NBk, 256>>>(weight_l);
    embed_kernel<<<(NN * Dd / 4) / 256, 256>>>(x, emb);

    dim3 gD(Dd / 128, NN / 128);
    dim3 gU(2 * Ii / 128, NN / 128);
    dim3 gV(Vv / 128, NN / 128);
    const int scanBlocks = (Bb * CH * Dd) / 256;

    for (int i = 0; i < NBk; i++) {
        const float* wgin = wg_in   + i * Dd;
        const float* wgf  = wg_f    + i * Dd;
        const float* wgc  = wg_c    + i * Dd;
        const float* wgg  = wg_g    + i * Dd;
        const float* wgn  = wg_norm + i * Dd;
        const float* wgo  = wg_o    + i * Dd;
        const float* gwg  = glu_wg  + i * Dd;
        const float* gwgo = glu_wgo + i * Dd;
        const float* gwd  = glu_wd  + i * Ii;

        // combined row scale for rms(rms(y, wg_in), *) chain
        rms_rows_kernel<<<NN, 256>>>(pY, wgin, prA, Dd);

        int tD = Dd * Dd / 4;
        // f / c / g projections: col scales folded into weights, row scale in epilogue
        wscale_kernel<<<(tD + 255) / 256, 256>>>((const float4*)(lf_w + (size_t)i*Dd*Dd), wgin, wgf, (float4*)pWS, Dd/4, tD);
        tc_gemm<<<gD, 256, GEMM_SMEM_BYTES>>>(Dd, Dd, pY, pWS, prA, lf_b + i*Dd, nullptr, pZF);
        wscale_kernel<<<(tD + 255) / 256, 256>>>((const float4*)(lc_w + (size_t)i*Dd*Dd), wgin, wgc, (float4*)pWS, Dd/4, tD);
        tc_gemm<<<gD, 256, GEMM_SMEM_BYTES>>>(Dd, Dd, pY, pWS, prA, lc_b + i*Dd, nullptr, pZC);
        wscale_kernel<<<(tD + 255) / 256, 256>>>((const float4*)(lg_w + (size_t)i*Dd*Dd), wgin, wgg, (float4*)pWS, Dd/4, tD);
        tc_gemm<<<gD, 256, GEMM_SMEM_BYTES>>>(Dd, Dd, pY, pWS, prA, lg_b + i*Dd, nullptr, pZG);

        // gated recurrence over t: 2-pass chunked scan
        scan1_kernel<<<scanBlocks, 256>>>(pZF, pZC, pLB + i * Dd);
        scan2_kernel<<<scanBlocks, 256>>>(pZF, pZC, pLB + i * Dd, pH);

        // x_g = rms(zg, wg_norm); s = x_g * h * sigmoid(h); its row rms
        rms_rows_kernel<<<NN, 256>>>(pZG, nullptr, prB, Dd);
        s_kernel<<<NN, 256>>>(pZG, prB, wgn, pH, pS, prB);

        // x_o = y + rms(s, wg_o_out) @ lo_w^T + lo_b
        wscale_kernel<<<(tD + 255) / 256, 256>>>((const float4*)(lo_w + (size_t)i*Dd*Dd), wgo, nullptr, (float4*)pWS, Dd/4, tD);
        tc_gemm<<<gD, 256, GEMM_SMEM_BYTES>>>(Dd, Dd, pS, pWS, prB, lo_b + i*Dd, pY, pXO);

        // GLU up-proj: combined rms(rms(x_o, glu_wg), glu_wgo) scale
        rms_rows_kernel<<<NN, 256>>>(pXO, gwg, prA, Dd);
        int tU = 2 * Ii * Dd / 4;
        wscale_kernel<<<(tU + 255) / 256, 256>>>((const float4*)(lu_w + (size_t)i*2*Ii*Dd), gwg, gwgo, (float4*)pWS, Dd/4, tU);
        tc_gemm<<<gU, 256, GEMM_SMEM_BYTES>>>(2 * Ii, Dd, pXO, pWS, prA, lu_b + (size_t)i*2*Ii, nullptr, pUU);
        glu_kernel<<<NN, 256>>>(pUU, pGP, prB);

        // y_next = x_o + rms(gp, glu_wd) @ ln_w^T + ln_b
        int tN = Dd * Ii / 4;
        wscale_kernel<<<(tN + 255) / 256, 256>>>((const float4*)(ln_w + (size_t)i*Dd*Ii), gwd, nullptr, (float4*)pWS, Ii/4, tN);
        tc_gemm<<<gD, 256, GEMM_SMEM_BYTES>>>(Dd, Ii, pGP, pWS, prB, ln_b + i*Dd, pXO, pY);
    }

    // logits = y @ out_w^T + out_b  -> [B,T,V]
    tc_gemm<<<gV, 256, GEMM_SMEM_BYTES>>>(Vv, Dd, pY, out_w, nullptr, out_b, nullptr, out);
}

// round 5
// speedup vs baseline: 4.1646x; 1.0831x over previous
#include <cuda_runtime.h>
#include <cstdint>
#include <math.h>

#define NBk 4
#define Bb  8
#define Tt  1024
#define Dd  1024
#define Vv  256
#define Ii  2816
#define NN  (Bb*Tt)      // 8192 tokens
#define EPSf 1e-6f
#define TC  128          // scan chunk length
#define CH  (Tt/TC)      // 8 chunks

// ---------------- scratch (device globals; no allocation allowed) ------------
__device__ float g_Y [NN*Dd];
__device__ float g_ZF[NN*Dd];
__device__ float g_ZC[NN*Dd];
__device__ float g_ZG[NN*Dd];
__device__ float g_H [NN*Dd];
__device__ float g_S [NN*Dd];
__device__ float g_XO[NN*Dd];
__device__ float g_XS[NN*Dd];             // scaled copy of XO for the lu gemm
__device__ float g_UU[(size_t)NN*2*Ii];
__device__ float g_GP[(size_t)NN*Ii];
__device__ float g_WS[(size_t)Dd*Dd];     // scaled-weight scratch (D x D only now)
__device__ float g_rA[NN];
__device__ float g_rB[NN];
__device__ float g_LB[NBk*Dd];
__device__ float g_SA[Bb*CH*Dd];
__device__ float g_SB[Bb*CH*Dd];

// ---------------- PTX helpers -------------------------------------------------
__device__ __forceinline__ uint32_t smem_u32(const void* p) {
    uint32_t a;
    asm("{ .reg .u64 t; cvta.to.shared.u64 t, %1; cvt.u32.u64 %0, t; }" : "=r"(a) : "l"(p));
    return a;
}
static __device__ __forceinline__ void cp16(uint32_t saddr, const void* gaddr) {
    asm volatile("cp.async.cg.shared.global [%0], [%1], 16;" :: "r"(saddr), "l"(gaddr));
}
static __device__ __forceinline__ void cp_commit() {
    asm volatile("cp.async.commit_group;" ::: "memory");
}
// plain shared load
static __device__ __forceinline__ uint32_t lds32(uint32_t addr) {
    uint32_t x;
    asm volatile("ld.shared.b32 %0, [%1];" : "=r"(x) : "r"(addr));
    return x;
}
// shared load + round-to-tf32 (RNA)
static __device__ __forceinline__ uint32_t ldcvt(uint32_t addr) {
    uint32_t x;
    asm volatile("ld.shared.b32 %0, [%1];" : "=r"(x) : "r"(addr));
    asm("cvt.rna.tf32.f32 %0, %0;" : "+r"(x));
    return x;
}
static __device__ __forceinline__ void mma_tf32(float* c, uint32_t a0, uint32_t a1,
                                                uint32_t a2, uint32_t a3,
                                                uint32_t b0, uint32_t b1) {
    asm volatile("mma.sync.aligned.m16n8k8.row.col.f32.tf32.tf32.f32 "
        "{%0,%1,%2,%3},{%4,%5,%6,%7},{%8,%9},{%0,%1,%2,%3};"
        : "+f"(c[0]), "+f"(c[1]), "+f"(c[2]), "+f"(c[3])
        : "r"(a0), "r"(a1), "r"(a2), "r"(a3), "r"(b0), "r"(b1));
}

#define GEMM_SMEM_BYTES (1024 + 6*16384)   // align slack + 3 stages x (A16K + B16K)

// ---------------- tensor-core GEMM (mma.sync tf32, 4 warps 64x64) ------------
// C[n, m] = rs[n] * sum_k A[n,k]*W[m,k] + bias[m] (+ addC[n,m])
// optional C2[n, m] = C[n,m] * cs2a[m]*cs2b[m]
// A [N,K] rm, W [M,K] rm. grid = (M/128, N/128), 128 threads. K mult of 32.
template<bool CVTB>
__global__ void __launch_bounds__(128, 2)
tc_gemm(int M, int K,
        const float* __restrict__ A, const float* __restrict__ W,
        const float* __restrict__ rowscale, const float* __restrict__ bias,
        const float* __restrict__ addC, float* __restrict__ C,
        float* __restrict__ C2, const float* __restrict__ cs2a,
        const float* __restrict__ cs2b)
{
    extern __shared__ char smem_raw[];
    uint32_t base = (smem_u32(smem_raw) + 1023u) & ~1023u;
    uint32_t Aoff = base;
    uint32_t Boff = base + 3 * 16384;

    const int tid  = threadIdx.x;
    const int wid  = tid >> 5, lane = tid & 31;
    const int g    = lane >> 2, tig = lane & 3;
    const int rowA = blockIdx.y << 7;
    const int colB = blockIdx.x << 7;
    const int KT   = K >> 5;

    const int m_base = (wid >> 1) * 64;   // 0 or 64
    const int n_base = (wid & 1) * 64;    // 0 or 64

    // per-subtile row base bytes + swizzle masks (SW128: mask = (row*16)&0x70)
    uint32_t aRB[4][2], aMK[4][2], bRB[8], bMK[8];
    #pragma unroll
    for (int mi = 0; mi < 4; mi++) {
        int r0 = m_base + mi * 16 + g;
        int r1 = r0 + 8;
        aRB[mi][0] = (uint32_t)r0 << 7; aMK[mi][0] = ((uint32_t)r0 << 4) & 0x70u;
        aRB[mi][1] = (uint32_t)r1 << 7; aMK[mi][1] = ((uint32_t)r1 << 4) & 0x70u;
    }
    #pragma unroll
    for (int ni = 0; ni < 8; ni++) {
        int nr = n_base + ni * 8 + g;
        bRB[ni] = (uint32_t)nr << 7; bMK[ni] = ((uint32_t)nr << 4) & 0x70u;
    }

    float acc[4][8][4];
    #pragma unroll
    for (int mi = 0; mi < 4; mi++)
        #pragma unroll
        for (int ni = 0; ni < 8; ni++)
            #pragma unroll
            for (int q = 0; q < 4; q++) acc[mi][ni][q] = 0.f;

    // ---- tile loader: k-chunk kt into stage s (SW128 swizzled) ----
    #define LOAD_CHUNK(kt_, s_) do { \
        uint32_t _sA = Aoff + (s_) * 16384, _sB = Boff + (s_) * 16384; \
        const float* _Ab = A + (size_t)rowA * K + (size_t)(kt_) * 32; \
        const float* _Wb = W + (size_t)colB * K + (size_t)(kt_) * 32; \
        _Pragma("unroll") \
        for (int _i = 0; _i < 8; _i++) { \
            int _idx = tid + _i * 128; \
            int _r = _idx >> 3, _seg = _idx & 7; \
            uint32_t _b = ((uint32_t)_r << 7) + ((uint32_t)_seg << 4); \
            uint32_t _sw = _b ^ ((_b >> 3) & 0x70u); \
            cp16(_sA + _sw, _Ab + (size_t)_r * K + _seg * 4); \
            cp16(_sB + _sw, _Wb + (size_t)_r * K + _seg * 4); \
        } \
        cp_commit(); \
    } while (0)

    LOAD_CHUNK(0, 0);
    LOAD_CHUNK(1, 1);

    for (int kt = 0; kt < KT; kt++) {
        const int s = kt % 3;
        if (kt + 1 < KT) asm volatile("cp.async.wait_group 1;" ::: "memory");
        else             asm volatile("cp.async.wait_group 0;" ::: "memory");
        __syncthreads();
        if (kt + 2 < KT) LOAD_CHUNK(kt + 2, (kt + 2) % 3);

        const uint32_t aS = Aoff + s * 16384;
        const uint32_t bS = Boff + s * 16384;
        #pragma unroll
        for (int kk = 0; kk < 4; kk++) {
            const uint32_t c0b = (uint32_t)(kk * 8 + tig) << 2;
            const uint32_t c1b = c0b + 16u;
            uint32_t bf[8][2];
            #pragma unroll
            for (int ni = 0; ni < 8; ni++) {
                if (CVTB) {
                    bf[ni][0] = ldcvt(bS + bRB[ni] + (c0b ^ bMK[ni]));
                    bf[ni][1] = ldcvt(bS + bRB[ni] + (c1b ^ bMK[ni]));
                } else {
                    bf[ni][0] = lds32(bS + bRB[ni] + (c0b ^ bMK[ni]));
                    bf[ni][1] = lds32(bS + bRB[ni] + (c1b ^ bMK[ni]));
                }
            }
            #pragma unroll
            for (int mi = 0; mi < 4; mi++) {
                uint32_t a0 = ldcvt(aS + aRB[mi][0] + (c0b ^ aMK[mi][0]));
                uint32_t a1 = ldcvt(aS + aRB[mi][1] + (c0b ^ aMK[mi][1]));
                uint32_t a2 = ldcvt(aS + aRB[mi][0] + (c1b ^ aMK[mi][0]));
                uint32_t a3 = ldcvt(aS + aRB[mi][1] + (c1b ^ aMK[mi][1]));
                #pragma unroll
                for (int ni = 0; ni < 8; ni++)
                    mma_tf32(acc[mi][ni], a0, a1, a2, a3, bf[ni][0], bf[ni][1]);
            }
        }
    }

    // ---- epilogue: rowscale, bias, optional residual, optional scaled copy ----
    #pragma unroll
    for (int mi = 0; mi < 4; mi++) {
        const int row0 = rowA + m_base + mi * 16 + g;
        const int row1 = row0 + 8;
        const float rs0 = rowscale ? rowscale[row0] : 1.0f;
        const float rs1 = rowscale ? rowscale[row1] : 1.0f;
        #pragma unroll
        for (int ni = 0; ni < 8; ni++) {
            const int col = colB + n_base + ni * 8 + 2 * tig;
            float2 bv = *(const float2*)(bias + col);
            size_t o0 = (size_t)row0 * M + col;
            size_t o1 = (size_t)row1 * M + col;
            float2 v0, v1;
            v0.x = acc[mi][ni][0] * rs0 + bv.x;
            v0.y = acc[mi][ni][1] * rs0 + bv.y;
            v1.x = acc[mi][ni][2] * rs1 + bv.x;
            v1.y = acc[mi][ni][3] * rs1 + bv.y;
            if (addC) {
                float2 r0 = *(const float2*)(addC + o0);
                float2 r1 = *(const float2*)(addC + o1);
                v0.x += r0.x; v0.y += r0.y;
                v1.x += r1.x; v1.y += r1.y;
            }
            *(float2*)(C + o0) = v0;
            *(float2*)(C + o1) = v1;
            if (C2) {
                float2 sa = *(const float2*)(cs2a + col);
                float2 sb = *(const float2*)(cs2b + col);
                float2 w0, w1;
                w0.x = v0.x * sa.x * sb.x; w0.y = v0.y * sa.y * sb.y;
                w1.x = v1.x * sa.x * sb.x; w1.y = v1.y * sa.y * sb.y;
                *(float2*)(C2 + o0) = w0;
                *(float2*)(C2 + o1) = w1;
            }
        }
    }
    #undef LOAD_CHUNK
}

// ---------------- weight pre-scale: Wo = cvt_tf32(W*c1*c2) -------------------
__global__ void wscale_kernel(const float4* __restrict__ W, const float* __restrict__ c1,
                              const float* __restrict__ c2, float4* __restrict__ Wo,
                              int K4, int total4) {
    int i = blockIdx.x * blockDim.x + threadIdx.x;
    if (i >= total4) return;
    int k4 = i % K4;
    float4 w = W[i];
    float4 a = ((const float4*)c1)[k4];
    float4 b = ((const float4*)c2)[k4];
    w.x *= a.x * b.x; w.y *= a.y * b.y; w.z *= a.z * b.z; w.w *= a.w * b.w;
    asm("cvt.rna.tf32.f32 %0, %0;" : "+f"(w.x));
    asm("cvt.rna.tf32.f32 %0, %0;" : "+f"(w.y));
    asm("cvt.rna.tf32.f32 %0, %0;" : "+f"(w.z));
    asm("cvt.rna.tf32.f32 %0, %0;" : "+f"(w.w));
    Wo[i] = w;
}

// ---------------- small helpers ----------------------------------------------
__device__ __forceinline__ float sigm(float x) { return 1.f / (1.f + __expf(-x)); }

__device__ __forceinline__ float blockReduce1(float s1) {
    __shared__ float r1[256];
    int t = threadIdx.x;
    r1[t] = s1; __syncthreads();
    for (int s = 128; s > 0; s >>= 1) {
        if (t < s) r1[t] += r1[t+s];
        __syncthreads();
    }
    float v = r1[0];
    __syncthreads();
    return v;
}
__device__ __forceinline__ void blockReduce2(float& s1, float& s2) {
    __shared__ float r1[256], r2[256];
    int t = threadIdx.x;
    r1[t] = s1; r2[t] = s2; __syncthreads();
    for (int s = 128; s > 0; s >>= 1) {
        if (t < s) { r1[t] += r1[t+s]; r2[t] += r2[t+s]; }
        __syncthreads();
    }
    s1 = r1[0]; s2 = r2[0];
    __syncthreads();
}

// ---------------- lb = cumsum(softmax(weight_l)) - weight_l[:, :1] -----------
__global__ void lb_kernel(const float* __restrict__ wl) {
    __shared__ float sm[Dd];
    __shared__ float red[256];
    int i = blockIdx.x;
    const float* w = wl + i * Dd;
    int t = threadIdx.x;
    float mx = -1e30f;
    for (int d = t; d < Dd; d += 256) mx = fmaxf(mx, w[d]);
    red[t] = mx; __syncthreads();
    for (int s = 128; s > 0; s >>= 1) { if (t < s) red[t] = fmaxf(red[t], red[t+s]); __syncthreads(); }
    mx = red[0]; __syncthreads();
    float sum = 0.f;
    for (int d = t; d < Dd; d += 256) { float e = expf(w[d] - mx); sm[d] = e; sum += e; }
    red[t] = sum; __syncthreads();
    for (int s = 128; s > 0; s >>= 1) { if (t < s) red[t] += red[t+s]; __syncthreads(); }
    float Z = red[0];
    float w0 = w[0];
    __syncthreads();
    for (int d = t; d < Dd; d += 256) {
        float c = 0.f;
        for (int k = 0; k <= d; k++) c += sm[k];
        g_LB[i * Dd + d] = c / Z - w0;
    }
}

// ---------------- y = emb[x] --------------------------------------------------
__global__ void embed_kernel(const int* __restrict__ x, const float* __restrict__ emb) {
    int idx = blockIdx.x * blockDim.x + threadIdx.x;
    int n  = idx / (Dd/4);
    int d4 = idx % (Dd/4);
    int b = n / Tt, t = n % Tt;
    int tok = x[b * Tt + t];
    ((float4*)g_Y)[(size_t)n * (Dd/4) + d4] = ((const float4*)(emb + (size_t)tok * Dd))[d4];
}

// ---------------- row rms stats (combined double-rms scale) ------------------
__global__ void rms_rows_kernel(const float* __restrict__ X, const float* __restrict__ w,
                                float* __restrict__ out, int D) {
    int n = blockIdx.x;
    const float* x = X + (size_t)n * D;
    float s1 = 0.f, s2 = 0.f;
    for (int d = threadIdx.x; d < D; d += 256) {
        float v = x[d];
        s1 += v * v;
        float vw = v * w[d]; s2 += vw * vw;
    }
    blockReduce2(s1, s2);
    if (threadIdx.x == 0) {
        float r1 = rsqrtf(s1 / D + EPSf);
        float r2 = rsqrtf(r1 * r1 * s2 / D + EPSf);
        out[n] = r1 * r2;
    }
}

// ---------------- chunked linear-recurrence scan ------------------------------
__global__ void scan1_kernel(const float* __restrict__ ZF, const float* __restrict__ ZC,
                             const float* __restrict__ lbrow) {
    int id = blockIdx.x * blockDim.x + threadIdx.x;    // Bb*CH*Dd
    int d = id % Dd;
    int c = (id / Dd) % CH;
    int b = id / (Dd * CH);
    float l = lbrow[d];
    size_t base = ((size_t)b * Tt + (size_t)c * TC) * Dd + d;
    float a = 1.f, h = 0.f;
    for (int t = 0; t < TC; t++) {
        float f  = l + (1.f - l) * sigm(ZF[base + (size_t)t * Dd]);
        float zv = ZC[base + (size_t)t * Dd];
        float cc = zv * sigm(zv);
        h = f * h + (1.f - f) * cc;
        a *= f;
    }
    g_SA[id] = a;
    g_SB[id] = h;
}
__global__ void scan2_kernel(const float* __restrict__ ZF, const float* __restrict__ ZC,
                             const float* __restrict__ lbrow, float* __restrict__ H) {
    int id = blockIdx.x * blockDim.x + threadIdx.x;
    int d = id % Dd;
    int c = (id / Dd) % CH;
    int b = id / (Dd * CH);
    float l = lbrow[d];
    float h = 0.f;
    for (int j = 0; j < c; j++) {
        int sid = (b * CH + j) * Dd + d;
        h = g_SA[sid] * h + g_SB[sid];
    }
    size_t base = ((size_t)b * Tt + (size_t)c * TC) * Dd + d;
    for (int t = 0; t < TC; t++) {
        float f  = l + (1.f - l) * sigm(ZF[base + (size_t)t * Dd]);
        float zv = ZC[base + (size_t)t * Dd];
        float cc = zv * sigm(zv);
        h = f * h + (1.f - f) * cc;
        H[base + (size_t)t * Dd] = h;
    }
}

// ---------------- fused: rz = rms(ZG); s = xg*h*sig(h); S = s*wgo; rB --------
__global__ void s_fused_kernel(const float* __restrict__ ZG, const float* __restrict__ wnorm,
                               const float* __restrict__ H, const float* __restrict__ wgo,
                               float* __restrict__ S, float* __restrict__ rs_out) {
    __shared__ float zbuf[Dd];
    int n = blockIdx.x;
    float s1 = 0.f;
    for (int d = threadIdx.x; d < Dd; d += 256) {
        float v = ZG[(size_t)n * Dd + d];
        zbuf[d] = v;
        s1 += v * v;
    }
    float rz = rsqrtf(blockReduce1(s1) / Dd + EPSf);
    float s2 = 0.f;
    for (int d = threadIdx.x; d < Dd; d += 256) {
        size_t o = (size_t)n * Dd + d;
        float xg = zbuf[d] * rz * wnorm[d];
        float h  = H[o];
        float s  = xg * h * sigm(h);
        S[o] = s * wgo[d];
        s2 += s * s;
    }
    s2 = blockReduce1(s2);
    if (threadIdx.x == 0) rs_out[n] = rsqrtf(s2 / Dd + EPSf);
}

// ---------------- fused GLU: gp = silu(u0)*u1; GP = gp*gwd; rg ---------------
__global__ void glu_kernel(const float* __restrict__ UU, const float* __restrict__ gwd,
                           float* __restrict__ GP, float* __restrict__ rg) {
    int n = blockIdx.x;
    const float* u = UU + (size_t)n * 2 * Ii;
    float s2 = 0.f;
    for (int k = threadIdx.x; k < Ii; k += 256) {
        float a = u[k], b = u[Ii + k];
        float gv = a * sigm(a) * b;
        GP[(size_t)n * Ii + k] = gv * gwd[k];
        s2 += gv * gv;
    }
    s2 = blockReduce1(s2);
    if (threadIdx.x == 0) rg[n] = rsqrtf(s2 / Ii + EPSf);
}

// ---------------- launcher ----------------------------------------------------
extern "C" void kernel_launch(void* const* d_in, const int* in_sizes, int n_in,
                              void* d_out, int out_size) {
    const int*   x       = (const int*)  d_in[0];
    const float* emb     = (const float*)d_in[1];
    const float* wg_in   = (const float*)d_in[2];
    const float* wg_f    = (const float*)d_in[3];
    const float* wg_c    = (const float*)d_in[4];
    const float* wg_g    = (const float*)d_in[5];
    const float* wg_norm = (const float*)d_in[6];
    const float* lf_w    = (const float*)d_in[7];
    const float* lf_b    = (const float*)d_in[8];
    const float* lc_w    = (const float*)d_in[9];
    const float* lc_b    = (const float*)d_in[10];
    const float* lg_w    = (const float*)d_in[11];
    const float* lg_b    = (const float*)d_in[12];
    const float* weight_l= (const float*)d_in[13];
    const float* wg_o    = (const float*)d_in[14];
    const float* lo_w    = (const float*)d_in[15];
    const float* lo_b    = (const float*)d_in[16];
    const float* glu_wg  = (const float*)d_in[17];
    const float* glu_wgo = (const float*)d_in[18];
    const float* glu_wd  = (const float*)d_in[19];
    const float* lu_w    = (const float*)d_in[20];
    const float* lu_b    = (const float*)d_in[21];
    const float* ln_w    = (const float*)d_in[22];
    const float* ln_b    = (const float*)d_in[23];
    const float* out_w   = (const float*)d_in[24];
    const float* out_b   = (const float*)d_in[25];
    float* out = (float*)d_out;

    float *pY, *pZF, *pZC, *pZG, *pH, *pS, *pXO, *pXS, *pUU, *pGP, *pWS, *prA, *prB, *pLB;
    cudaGetSymbolAddress((void**)&pY,  g_Y);
    cudaGetSymbolAddress((void**)&pZF, g_ZF);
    cudaGetSymbolAddress((void**)&pZC, g_ZC);
    cudaGetSymbolAddress((void**)&pZG, g_ZG);
    cudaGetSymbolAddress((void**)&pH,  g_H);
    cudaGetSymbolAddress((void**)&pS,  g_S);
    cudaGetSymbolAddress((void**)&pXO, g_XO);
    cudaGetSymbolAddress((void**)&pXS, g_XS);
    cudaGetSymbolAddress((void**)&pUU, g_UU);
    cudaGetSymbolAddress((void**)&pGP, g_GP);
    cudaGetSymbolAddress((void**)&pWS, g_WS);
    cudaGetSymbolAddress((void**)&prA, g_rA);
    cudaGetSymbolAddress((void**)&prB, g_rB);
    cudaGetSymbolAddress((void**)&pLB, g_LB);

    cudaFuncSetAttribute(tc_gemm<false>, cudaFuncAttributeMaxDynamicSharedMemorySize, GEMM_SMEM_BYTES);
    cudaFuncSetAttribute(tc_gemm<true>,  cudaFuncAttributeMaxDynamicSharedMemorySize, GEMM_SMEM_BYTES);

    lb_kernel<<<NBk, 256>>>(weight_l);
    embed_kernel<<<(NN * Dd / 4) / 256, 256>>>(x, emb);

    dim3 gD(Dd / 128, NN / 128);
    dim3 gU(2 * Ii / 128, NN / 128);
    dim3 gV(Vv / 128, NN / 128);
    const int scanBlocks = (Bb * CH * Dd) / 256;
    const int tD = Dd * Dd / 4;

    for (int i = 0; i < NBk; i++) {
        const float* wgin = wg_in   + i * Dd;
        const float* wgf  = wg_f    + i * Dd;
        const float* wgc  = wg_c    + i * Dd;
        const float* wgg  = wg_g    + i * Dd;
        const float* wgn  = wg_norm + i * Dd;
        const float* wgo  = wg_o    + i * Dd;
        const float* gwg  = glu_wg  + i * Dd;
        const float* gwgo = glu_wgo + i * Dd;
        const float* gwd  = glu_wd  + i * Ii;

        // combined row scale for rms(rms(y, wg_in), *) chain
        rms_rows_kernel<<<NN, 256>>>(pY, wgin, prA, Dd);

        // f / c / g projections: col scales + tf32 rounding folded into weights
        wscale_kernel<<<(tD + 255) / 256, 256>>>((const float4*)(lf_w + (size_t)i*Dd*Dd), wgin, wgf, (float4*)pWS, Dd/4, tD);
        tc_gemm<false><<<gD, 128, GEMM_SMEM_BYTES>>>(Dd, Dd, pY, pWS, prA, lf_b + i*Dd, nullptr, pZF, nullptr, nullptr, nullptr);
        wscale_kernel<<<(tD + 255) / 256, 256>>>((const float4*)(lc_w + (size_t)i*Dd*Dd), wgin, wgc, (float4*)pWS, Dd/4, tD);
        tc_gemm<false><<<gD, 128, GEMM_SMEM_BYTES>>>(Dd, Dd, pY, pWS, prA, lc_b + i*Dd, nullptr, pZC, nullptr, nullptr, nullptr);
        wscale_kernel<<<(tD + 255) / 256, 256>>>((const float4*)(lg_w + (size_t)i*Dd*Dd), wgin, wgg, (float4*)pWS, Dd/4, tD);
        tc_gemm<false><<<gD, 128, GEMM_SMEM_BYTES>>>(Dd, Dd, pY, pWS, prA, lg_b + i*Dd, nullptr, pZG, nullptr, nullptr, nullptr);

        // gated recurrence over t: 2-pass chunked scan
        scan1_kernel<<<scanBlocks, 256>>>(pZF, pZC, pLB + i * Dd);
        scan2_kernel<<<scanBlocks, 256>>>(pZF, pZC, pLB + i * Dd, pH);

        // fused: x_g row-rms + s = x_g*h*sig(h), S = s*wgo (col scale folded)
        s_fused_kernel<<<NN, 256>>>(pZG, wgn, pH, wgo, pS, prB);

        // x_o = y + rms(s, wg_o) @ lo_w^T + lo_b ; also emit XO_s = XO*gwg*gwgo
        tc_gemm<true><<<gD, 128, GEMM_SMEM_BYTES>>>(Dd, Dd, pS, lo_w + (size_t)i*Dd*Dd, prB, lo_b + i*Dd, pY, pXO, pXS, gwg, gwgo);

        // GLU up-proj row scale, then UU = XO_s @ lu_w^T + lu_b
        rms_rows_kernel<<<NN, 256>>>(pXO, gwg, prA, Dd);
        tc_gemm<true><<<gU, 128, GEMM_SMEM_BYTES>>>(2 * Ii, Dd, pXS, lu_w + (size_t)i*2*Ii*Dd, prA, lu_b + (size_t)i*2*Ii, nullptr, pUU, nullptr, nullptr, nullptr);

        // fused GLU gate (col scale gwd folded into GP)
        glu_kernel<<<NN, 256>>>(pUU, gwd, pGP, prB);

        // y_next = x_o + rms(gp, glu_wd) @ ln_w^T + ln_b
        tc_gemm<true><<<gD, 128, GEMM_SMEM_BYTES>>>(Dd, Ii, pGP, ln_w + (size_t)i*Dd*Ii, prB, ln_b + i*Dd, pXO, pY, nullptr, nullptr, nullptr);
    }

    // logits = y @ out_w^T + out_b  -> [B,T,V]
    tc_gemm<true><<<gV, 128, GEMM_SMEM_BYTES>>>(Vv, Dd, pY, out_w, nullptr, out_b, nullptr, out, nullptr, nullptr, nullptr);
}

// round 7
// speedup vs baseline: 4.4305x; 1.0639x over previous
#include <cuda_runtime.h>
#include <cstdint>
#include <math.h>

#define NBk 4
#define Bb  8
#define Tt  1024
#define Dd  1024
#define Vv  256
#define Ii  2816
#define NN  (Bb*Tt)      // 8192 tokens
#define EPSf 1e-6f
#define TC  128          // scan chunk length
#define CH  (Tt/TC)      // 8 chunks

// ---------------- scratch (device globals; no allocation allowed) ------------
__device__ float g_Y [NN*Dd];
__device__ float g_YT[NN*Dd];             // tf32-rounded copy of Y (GEMM A operand)
__device__ float g_ZF[NN*Dd];
__device__ float g_ZC[NN*Dd];
__device__ float g_ZG[NN*Dd];
__device__ float g_H [NN*Dd];
__device__ float g_S [NN*Dd];
__device__ float g_XO[NN*Dd];
__device__ float g_XS[NN*Dd];             // tf32-rounded scaled copy of XO
__device__ float g_UU[(size_t)NN*2*Ii];
__device__ float g_GP[(size_t)NN*Ii];
__device__ float g_WS[(size_t)2*Ii*Dd];   // pre-rounded weight scratch (max 2I x D)
__device__ float g_rA[NN];
__device__ float g_rB[NN];
__device__ float g_LB[NBk*Dd];
__device__ float g_SA[Bb*CH*Dd];
__device__ float g_SB[Bb*CH*Dd];

// ---------------- PTX helpers -------------------------------------------------
__device__ __forceinline__ uint32_t smem_u32(const void* p) {
    uint32_t a;
    asm("{ .reg .u64 t; cvta.to.shared.u64 t, %1; cvt.u32.u64 %0, t; }" : "=r"(a) : "l"(p));
    return a;
}
static __device__ __forceinline__ void cp16(uint32_t saddr, const void* gaddr) {
    asm volatile("cp.async.cg.shared.global [%0], [%1], 16;" :: "r"(saddr), "l"(gaddr));
}
static __device__ __forceinline__ void cp_commit() {
    asm volatile("cp.async.commit_group;" ::: "memory");
}
static __device__ __forceinline__ uint32_t lds32(uint32_t addr) {
    uint32_t x;
    asm volatile("ld.shared.b32 %0, [%1];" : "=r"(x) : "r"(addr));
    return x;
}
static __device__ __forceinline__ float cvt_tf32(float v) {
    asm("cvt.rna.tf32.f32 %0, %0;" : "+f"(v));
    return v;
}
static __device__ __forceinline__ void mma_tf32(float* c, uint32_t a0, uint32_t a1,
                                                uint32_t a2, uint32_t a3,
                                                uint32_t b0, uint32_t b1) {
    asm volatile("mma.sync.aligned.m16n8k8.row.col.f32.tf32.tf32.f32 "
        "{%0,%1,%2,%3},{%4,%5,%6,%7},{%8,%9},{%0,%1,%2,%3};"
        : "+f"(c[0]), "+f"(c[1]), "+f"(c[2]), "+f"(c[3])
        : "r"(a0), "r"(a1), "r"(a2), "r"(a3), "r"(b0), "r"(b1));
}

#define GEMM_SMEM_BYTES (1024 + 6*16384)   // align slack + 3 stages x (A16K + B16K)

// ---------------- tensor-core GEMM (mma.sync tf32, 4 warps 64x64) ------------
// All operands MUST be pre-rounded to tf32.
// C[n, m] = rs[n] * sum_k A[n,k]*W[m,k] + bias[m] (+ addC[n,m])
// optional second output:
//   cs2a != null : C2[n,m] = cvt_tf32(C[n,m] * cs2a[m] * cs2b[m])
//   cs2a == null : C2[n,m] = cvt_tf32(C[n,m])
// A [N,K] rm, W [M,K] rm. grid = (M/128, N/128), 128 threads. K mult of 32.
__global__ void __launch_bounds__(128, 2)
tc_gemm(int M, int K,
        const float* __restrict__ A, const float* __restrict__ W,
        const float* __restrict__ rowscale, const float* __restrict__ bias,
        const float* __restrict__ addC, float* __restrict__ C,
        float* __restrict__ C2, const float* __restrict__ cs2a,
        const float* __restrict__ cs2b)
{
    extern __shared__ char smem_raw[];
    uint32_t base = (smem_u32(smem_raw) + 1023u) & ~1023u;
    uint32_t Aoff = base;
    uint32_t Boff = base + 3 * 16384;

    const int tid  = threadIdx.x;
    const int wid  = tid >> 5, lane = tid & 31;
    const int g    = lane >> 2, tig = lane & 3;
    const int rowA = blockIdx.y << 7;
    const int colB = blockIdx.x << 7;
    const int KT   = K >> 5;

    const int m_base = (wid >> 1) * 64;   // 0 or 64
    const int n_base = (wid & 1) * 64;    // 0 or 64

    // per-subtile row base bytes + swizzle masks (SW128: mask = (row*16)&0x70)
    uint32_t aRB[4][2], aMK[4][2], bRB[8], bMK[8];
    #pragma unroll
    for (int mi = 0; mi < 4; mi++) {
        int r0 = m_base + mi * 16 + g;
        int r1 = r0 + 8;
        aRB[mi][0] = (uint32_t)r0 << 7; aMK[mi][0] = ((uint32_t)r0 << 4) & 0x70u;
        aRB[mi][1] = (uint32_t)r1 << 7; aMK[mi][1] = ((uint32_t)r1 << 4) & 0x70u;
    }
    #pragma unroll
    for (int ni = 0; ni < 8; ni++) {
        int nr = n_base + ni * 8 + g;
        bRB[ni] = (uint32_t)nr << 7; bMK[ni] = ((uint32_t)nr << 4) & 0x70u;
    }

    float acc[4][8][4];
    #pragma unroll
    for (int mi = 0; mi < 4; mi++)
        #pragma unroll
        for (int ni = 0; ni < 8; ni++)
            #pragma unroll
            for (int q = 0; q < 4; q++) acc[mi][ni][q] = 0.f;

    // ---- tile loader: k-chunk kt into stage s (SW128 swizzled) ----
    #define LOAD_CHUNK(kt_, s_) do { \
        uint32_t _sA = Aoff + (s_) * 16384, _sB = Boff + (s_) * 16384; \
        const float* _Ab = A + (size_t)rowA * K + (size_t)(kt_) * 32; \
        const float* _Wb = W + (size_t)colB * K + (size_t)(kt_) * 32; \
        _Pragma("unroll") \
        for (int _i = 0; _i < 8; _i++) { \
            int _idx = tid + _i * 128; \
            int _r = _idx >> 3, _seg = _idx & 7; \
            uint32_t _b = ((uint32_t)_r << 7) + ((uint32_t)_seg << 4); \
            uint32_t _sw = _b ^ ((_b >> 3) & 0x70u); \
            cp16(_sA + _sw, _Ab + (size_t)_r * K + _seg * 4); \
            cp16(_sB + _sw, _Wb + (size_t)_r * K + _seg * 4); \
        } \
        cp_commit(); \
    } while (0)

    LOAD_CHUNK(0, 0);
    LOAD_CHUNK(1, 1);

    for (int kt = 0; kt < KT; kt++) {
        const int s = kt % 3;
        if (kt + 1 < KT) asm volatile("cp.async.wait_group 1;" ::: "memory");
        else             asm volatile("cp.async.wait_group 0;" ::: "memory");
        __syncthreads();
        if (kt + 2 < KT) LOAD_CHUNK(kt + 2, (kt + 2) % 3);

        const uint32_t aS = Aoff + s * 16384;
        const uint32_t bS = Boff + s * 16384;
        #pragma unroll
        for (int kk = 0; kk < 4; kk++) {
            const uint32_t c0b = (uint32_t)(kk * 8 + tig) << 2;
            const uint32_t c1b = c0b + 16u;
            uint32_t bf[8][2];
            #pragma unroll
            for (int ni = 0; ni < 8; ni++) {
                bf[ni][0] = lds32(bS + bRB[ni] + (c0b ^ bMK[ni]));
                bf[ni][1] = lds32(bS + bRB[ni] + (c1b ^ bMK[ni]));
            }
            #pragma unroll
            for (int mi = 0; mi < 4; mi++) {
                uint32_t a0 = lds32(aS + aRB[mi][0] + (c0b ^ aMK[mi][0]));
                uint32_t a1 = lds32(aS + aRB[mi][1] + (c0b ^ aMK[mi][1]));
                uint32_t a2 = lds32(aS + aRB[mi][0] + (c1b ^ aMK[mi][0]));
                uint32_t a3 = lds32(aS + aRB[mi][1] + (c1b ^ aMK[mi][1]));
                #pragma unroll
                for (int ni = 0; ni < 8; ni++)
                    mma_tf32(acc[mi][ni], a0, a1, a2, a3, bf[ni][0], bf[ni][1]);
            }
        }
    }

    // ---- epilogue: rowscale, bias, optional residual, optional rounded copy ----
    #pragma unroll
    for (int mi = 0; mi < 4; mi++) {
        const int row0 = rowA + m_base + mi * 16 + g;
        const int row1 = row0 + 8;
        const float rs0 = rowscale ? rowscale[row0] : 1.0f;
        const float rs1 = rowscale ? rowscale[row1] : 1.0f;
        #pragma unroll
        for (int ni = 0; ni < 8; ni++) {
            const int col = colB + n_base + ni * 8 + 2 * tig;
            float2 bv = *(const float2*)(bias + col);
            size_t o0 = (size_t)row0 * M + col;
            size_t o1 = (size_t)row1 * M + col;
            float2 v0, v1;
            v0.x = acc[mi][ni][0] * rs0 + bv.x;
            v0.y = acc[mi][ni][1] * rs0 + bv.y;
            v1.x = acc[mi][ni][2] * rs1 + bv.x;
            v1.y = acc[mi][ni][3] * rs1 + bv.y;
            if (addC) {
                float2 r0 = *(const float2*)(addC + o0);
                float2 r1 = *(const float2*)(addC + o1);
                v0.x += r0.x; v0.y += r0.y;
                v1.x += r1.x; v1.y += r1.y;
            }
            *(float2*)(C + o0) = v0;
            *(float2*)(C + o1) = v1;
            if (C2) {
                float2 w0, w1;
                if (cs2a) {
                    float2 sa = *(const float2*)(cs2a + col);
                    float2 sb = *(const float2*)(cs2b + col);
                    w0.x = cvt_tf32(v0.x * sa.x * sb.x); w0.y = cvt_tf32(v0.y * sa.y * sb.y);
                    w1.x = cvt_tf32(v1.x * sa.x * sb.x); w1.y = cvt_tf32(v1.y * sa.y * sb.y);
                } else {
                    w0.x = cvt_tf32(v0.x); w0.y = cvt_tf32(v0.y);
                    w1.x = cvt_tf32(v1.x); w1.y = cvt_tf32(v1.y);
                }
                *(float2*)(C2 + o0) = w0;
                *(float2*)(C2 + o1) = w1;
            }
        }
    }
    #undef LOAD_CHUNK
}

// ---------------- weight pre-scale: Wo = cvt_tf32(W*c1*c2) -------------------
__global__ void wscale_kernel(const float4* __restrict__ W, const float* __restrict__ c1,
                              const float* __restrict__ c2, float4* __restrict__ Wo,
                              int K4, int total4) {
    int i = blockIdx.x * blockDim.x + threadIdx.x;
    if (i >= total4) return;
    int k4 = i % K4;
    float4 w = W[i];
    float4 a = ((const float4*)c1)[k4];
    float4 b = ((const float4*)c2)[k4];
    w.x = cvt_tf32(w.x * a.x * b.x); w.y = cvt_tf32(w.y * a.y * b.y);
    w.z = cvt_tf32(w.z * a.z * b.z); w.w = cvt_tf32(w.w * a.w * b.w);
    Wo[i] = w;
}

// ---------------- weight pre-round: Wo = cvt_tf32(W) -------------------------
__global__ void wcvt_kernel(const float4* __restrict__ W, float4* __restrict__ Wo,
                            int total4) {
    int i = blockIdx.x * blockDim.x + threadIdx.x;
    if (i >= total4) return;
    float4 w = W[i];
    w.x = cvt_tf32(w.x); w.y = cvt_tf32(w.y);
    w.z = cvt_tf32(w.z); w.w = cvt_tf32(w.w);
    Wo[i] = w;
}

// ---------------- small helpers ----------------------------------------------
__device__ __forceinline__ float sigm(float x) { return 1.f / (1.f + __expf(-x)); }

__device__ __forceinline__ float blockReduce1(float s1) {
    __shared__ float r1[256];
    int t = threadIdx.x;
    r1[t] = s1; __syncthreads();
    for (int s = 128; s > 0; s >>= 1) {
        if (t < s) r1[t] += r1[t+s];
        __syncthreads();
    }
    float v = r1[0];
    __syncthreads();
    return v;
}
__device__ __forceinline__ void blockReduce2(float& s1, float& s2) {
    __shared__ float r1[256], r2[256];
    int t = threadIdx.x;
    r1[t] = s1; r2[t] = s2; __syncthreads();
    for (int s = 128; s > 0; s >>= 1) {
        if (t < s) { r1[t] += r1[t+s]; r2[t] += r2[t+s]; }
        __syncthreads();
    }
    s1 = r1[0]; s2 = r2[0];
    __syncthreads();
}

// ---------------- lb = cumsum(softmax(weight_l)) - weight_l[:, :1] -----------
__global__ void lb_kernel(const float* __restrict__ wl) {
    __shared__ float sm[Dd];
    __shared__ float red[256];
    int i = blockIdx.x;
    const float* w = wl + i * Dd;
    int t = threadIdx.x;
    float mx = -1e30f;
    for (int d = t; d < Dd; d += 256) mx = fmaxf(mx, w[d]);
    red[t] = mx; __syncthreads();
    for (int s = 128; s > 0; s >>= 1) { if (t < s) red[t] = fmaxf(red[t], red[t+s]); __syncthreads(); }
    mx = red[0]; __syncthreads();
    float sum = 0.f;
    for (int d = t; d < Dd; d += 256) { float e = expf(w[d] - mx); sm[d] = e; sum += e; }
    red[t] = sum; __syncthreads();
    for (int s = 128; s > 0; s >>= 1) { if (t < s) red[t] += red[t+s]; __syncthreads(); }
    float Z = red[0];
    float w0 = w[0];
    __syncthreads();
    for (int d = t; d < Dd; d += 256) {
        float c = 0.f;
        for (int k = 0; k <= d; k++) c += sm[k];
        g_LB[i * Dd + d] = c / Z - w0;
    }
}

// ---------------- y = emb[x]; yt = cvt_tf32(y) --------------------------------
__global__ void embed_kernel(const int* __restrict__ x, const float* __restrict__ emb) {
    int idx = blockIdx.x * blockDim.x + threadIdx.x;
    int n  = idx / (Dd/4);
    int d4 = idx % (Dd/4);
    int b = n / Tt, t = n % Tt;
    int tok = x[b * Tt + t];
    float4 v = ((const float4*)(emb + (size_t)tok * Dd))[d4];
    ((float4*)g_Y)[(size_t)n * (Dd/4) + d4] = v;
    v.x = cvt_tf32(v.x); v.y = cvt_tf32(v.y);
    v.z = cvt_tf32(v.z); v.w = cvt_tf32(v.w);
    ((float4*)g_YT)[(size_t)n * (Dd/4) + d4] = v;
}

// ---------------- row rms stats (combined double-rms scale) ------------------
__global__ void rms_rows_kernel(const float* __restrict__ X, const float* __restrict__ w,
                                float* __restrict__ out, int D) {
    int n = blockIdx.x;
    const float* x = X + (size_t)n * D;
    float s1 = 0.f, s2 = 0.f;
    for (int d = threadIdx.x; d < D; d += 256) {
        float v = x[d];
        s1 += v * v;
        float vw = v * w[d]; s2 += vw * vw;
    }
    blockReduce2(s1, s2);
    if (threadIdx.x == 0) {
        float r1 = rsqrtf(s1 / D + EPSf);
        float r2 = rsqrtf(r1 * r1 * s2 / D + EPSf);
        out[n] = r1 * r2;
    }
}

// ---------------- chunked linear-recurrence scan ------------------------------
__global__ void scan1_kernel(const float* __restrict__ ZF, const float* __restrict__ ZC,
                             const float* __restrict__ lbrow) {
    int id = blockIdx.x * blockDim.x + threadIdx.x;    // Bb*CH*Dd
    int d = id % Dd;
    int c = (id / Dd) % CH;
    int b = id / (Dd * CH);
    float l = lbrow[d];
    size_t base = ((size_t)b * Tt + (size_t)c * TC) * Dd + d;
    float a = 1.f, h = 0.f;
    for (int t = 0; t < TC; t++) {
        float f  = l + (1.f - l) * sigm(ZF[base + (size_t)t * Dd]);
        float zv = ZC[base + (size_t)t * Dd];
        float cc = zv * sigm(zv);
        h = f * h + (1.f - f) * cc;
        a *= f;
    }
    g_SA[id] = a;
    g_SB[id] = h;
}
__global__ void scan2_kernel(const float* __restrict__ ZF, const float* __restrict__ ZC,
                             const float* __restrict__ lbrow, float* __restrict__ H) {
    int id = blockIdx.x * blockDim.x + threadIdx.x;
    int d = id % Dd;
    int c = (id / Dd) % CH;
    int b = id / (Dd * CH);
    float l = lbrow[d];
    float h = 0.f;
    for (int j = 0; j < c; j++) {
        int sid = (b * CH + j) * Dd + d;
        h = g_SA[sid] * h + g_SB[sid];
    }
    size_t base = ((size_t)b * Tt + (size_t)c * TC) * Dd + d;
    for (int t = 0; t < TC; t++) {
        float f  = l + (1.f - l) * sigm(ZF[base + (size_t)t * Dd]);
        float zv = ZC[base + (size_t)t * Dd];
        float cc = zv * sigm(zv);
        h = f * h + (1.f - f) * cc;
        H[base + (size_t)t * Dd] = h;
    }
}

// ---------------- fused: rz = rms(ZG); s = xg*h*sig(h); S = cvt(s*wgo); rB ---
__global__ void s_fused_kernel(const float* __restrict__ ZG, const float* __restrict__ wnorm,
                               const float* __restrict__ H, const float* __restrict__ wgo,
                               float* __restrict__ S, float* __restrict__ rs_out) {
    __shared__ float zbuf[Dd];
    int n = blockIdx.x;
    float s1 = 0.f;
    for (int d = threadIdx.x; d < Dd; d += 256) {
        float v = ZG[(size_t)n * Dd + d];
        zbuf[d] = v;
        s1 += v * v;
    }
    float rz = rsqrtf(blockReduce1(s1) / Dd + EPSf);
    float s2 = 0.f;
    for (int d = threadIdx.x; d < Dd; d += 256) {
        size_t o = (size_t)n * Dd + d;
        float xg = zbuf[d] * rz * wnorm[d];
        float h  = H[o];
        float s  = xg * h * sigm(h);
        S[o] = cvt_tf32(s * wgo[d]);
        s2 += s * s;
    }
    s2 = blockReduce1(s2);
    if (threadIdx.x == 0) rs_out[n] = rsqrtf(s2 / Dd + EPSf);
}

// ---------------- fused GLU: gp = silu(u0)*u1; GP = cvt(gp*gwd); rg ----------
__global__ void glu_kernel(const float* __restrict__ UU, const float* __restrict__ gwd,
                           float* __restrict__ GP, float* __restrict__ rg) {
    int n = blockIdx.x;
    const float* u = UU + (size_t)n * 2 * Ii;
    float s2 = 0.f;
    for (int k = threadIdx.x; k < Ii; k += 256) {
        float a = u[k], b = u[Ii + k];
        float gv = a * sigm(a) * b;
        GP[(size_t)n * Ii + k] = cvt_tf32(gv * gwd[k]);
        s2 += gv * gv;
    }
    s2 = blockReduce1(s2);
    if (threadIdx.x == 0) rg[n] = rsqrtf(s2 / Ii + EPSf);
}

// ---------------- launcher ----------------------------------------------------
extern "C" void kernel_launch(void* const* d_in, const int* in_sizes, int n_in,
                              void* d_out, int out_size) {
    const int*   x       = (const int*)  d_in[0];
    const float* emb     = (const float*)d_in[1];
    const float* wg_in   = (const float*)d_in[2];
    const float* wg_f    = (const float*)d_in[3];
    const float* wg_c    = (const float*)d_in[4];
    const float* wg_g    = (const float*)d_in[5];
    const float* wg_norm = (const float*)d_in[6];
    const float* lf_w    = (const float*)d_in[7];
    const float* lf_b    = (const float*)d_in[8];
    const float* lc_w    = (const float*)d_in[9];
    const float* lc_b    = (const float*)d_in[10];
    const float* lg_w    = (const float*)d_in[11];
    const float* lg_b    = (const float*)d_in[12];
    const float* weight_l= (const float*)d_in[13];
    const float* wg_o    = (const float*)d_in[14];
    const float* lo_w    = (const float*)d_in[15];
    const float* lo_b    = (const float*)d_in[16];
    const float* glu_wg  = (const float*)d_in[17];
    const float* glu_wgo = (const float*)d_in[18];
    const float* glu_wd  = (const float*)d_in[19];
    const float* lu_w    = (const float*)d_in[20];
    const float* lu_b    = (const float*)d_in[21];
    const float* ln_w    = (const float*)d_in[22];
    const float* ln_b    = (const float*)d_in[23];
    const float* out_w   = (const float*)d_in[24];
    const float* out_b   = (const float*)d_in[25];
    float* out = (float*)d_out;

    float *pY, *pYT, *pZF, *pZC, *pZG, *pH, *pS, *pXO, *pXS, *pUU, *pGP, *pWS, *prA, *prB, *pLB;
    cudaGetSymbolAddress((void**)&pY,  g_Y);
    cudaGetSymbolAddress((void**)&pYT, g_YT);
    cudaGetSymbolAddress((void**)&pZF, g_ZF);
    cudaGetSymbolAddress((void**)&pZC, g_ZC);
    cudaGetSymbolAddress((void**)&pZG, g_ZG);
    cudaGetSymbolAddress((void**)&pH,  g_H);
    cudaGetSymbolAddress((void**)&pS,  g_S);
    cudaGetSymbolAddress((void**)&pXO, g_XO);
    cudaGetSymbolAddress((void**)&pXS, g_XS);
    cudaGetSymbolAddress((void**)&pUU, g_UU);
    cudaGetSymbolAddress((void**)&pGP, g_GP);
    cudaGetSymbolAddress((void**)&pWS, g_WS);
    cudaGetSymbolAddress((void**)&prA, g_rA);
    cudaGetSymbolAddress((void**)&prB, g_rB);
    cudaGetSymbolAddress((void**)&pLB, g_LB);

    cudaFuncSetAttribute(tc_gemm, cudaFuncAttributeMaxDynamicSharedMemorySize, GEMM_SMEM_BYTES);

    lb_kernel<<<NBk, 256>>>(weight_l);
    embed_kernel<<<(NN * Dd / 4) / 256, 256>>>(x, emb);

    dim3 gD(Dd / 128, NN / 128);
    dim3 gU(2 * Ii / 128, NN / 128);
    dim3 gV(Vv / 128, NN / 128);
    const int scanBlocks = (Bb * CH * Dd) / 256;
    const int tD = Dd * Dd / 4;
    const int tU = 2 * Ii * Dd / 4;
    const int tN = Dd * Ii / 4;

    for (int i = 0; i < NBk; i++) {
        const float* wgin = wg_in   + i * Dd;
        const float* wgf  = wg_f    + i * Dd;
        const float* wgc  = wg_c    + i * Dd;
        const float* wgg  = wg_g    + i * Dd;
        const float* wgn  = wg_norm + i * Dd;
        const float* wgo  = wg_o    + i * Dd;
        const float* gwg  = glu_wg  + i * Dd;
        const float* gwgo = glu_wgo + i * Dd;
        const float* gwd  = glu_wd  + i * Ii;

        // combined row scale for rms(rms(y, wg_in), *) chain (uses full-precision Y)
        rms_rows_kernel<<<NN, 256>>>(pY, wgin, prA, Dd);

        // f / c / g projections: col scales + tf32 rounding folded into weights;
        // A operand is pre-rounded YT
        wscale_kernel<<<(tD + 255) / 256, 256>>>((const float4*)(lf_w + (size_t)i*Dd*Dd), wgin, wgf, (float4*)pWS, Dd/4, tD);
        tc_gemm<<<gD, 128, GEMM_SMEM_BYTES>>>(Dd, Dd, pYT, pWS, prA, lf_b + i*Dd, nullptr, pZF, nullptr, nullptr, nullptr);
        wscale_kernel<<<(tD + 255) / 256, 256>>>((const float4*)(lc_w + (size_t)i*Dd*Dd), wgin, wgc, (float4*)pWS, Dd/4, tD);
        tc_gemm<<<gD, 128, GEMM_SMEM_BYTES>>>(Dd, Dd, pYT, pWS, prA, lc_b + i*Dd, nullptr, pZC, nullptr, nullptr, nullptr);
        wscale_kernel<<<(tD + 255) / 256, 256>>>((const float4*)(lg_w + (size_t)i*Dd*Dd), wgin, wgg, (float4*)pWS, Dd/4, tD);
        tc_gemm<<<gD, 128, GEMM_SMEM_BYTES>>>(Dd, Dd, pYT, pWS, prA, lg_b + i*Dd, nullptr, pZG, nullptr, nullptr, nullptr);

        // gated recurrence over t: 2-pass chunked scan
        scan1_kernel<<<scanBlocks, 256>>>(pZF, pZC, pLB + i * Dd);
        scan2_kernel<<<scanBlocks, 256>>>(pZF, pZC, pLB + i * Dd, pH);

        // fused: x_g row-rms + s = x_g*h*sig(h), S = cvt(s*wgo)
        s_fused_kernel<<<NN, 256>>>(pZG, wgn, pH, wgo, pS, prB);

        // x_o = y + rms(s, wg_o) @ lo_w^T + lo_b ; also XS = cvt(XO*gwg*gwgo)
        wcvt_kernel<<<(tD + 255) / 256, 256>>>((const float4*)(lo_w + (size_t)i*Dd*Dd), (float4*)pWS, tD);
        tc_gemm<<<gD, 128, GEMM_SMEM_BYTES>>>(Dd, Dd, pS, pWS, prB, lo_b + i*Dd, pY, pXO, pXS, gwg, gwgo);

        // GLU up-proj row scale, then UU = XS @ lu_w^T + lu_b
        rms_rows_kernel<<<NN, 256>>>(pXO, gwg, prA, Dd);
        wcvt_kernel<<<(tU + 255) / 256, 256>>>((const float4*)(lu_w + (size_t)i*2*Ii*Dd), (float4*)pWS, tU);
        tc_gemm<<<gU, 128, GEMM_SMEM_BYTES>>>(2 * Ii, Dd, pXS, pWS, prA, lu_b + (size_t)i*2*Ii, nullptr, pUU, nullptr, nullptr, nullptr);

        // fused GLU gate (col scale gwd folded, tf32-rounded)
        glu_kernel<<<NN, 256>>>(pUU, gwd, pGP, prB);

        // y_next = x_o + rms(gp, glu_wd) @ ln_w^T + ln_b ; also YT = cvt(y_next)
        wcvt_kernel<<<(tN + 255) / 256, 256>>>((const float4*)(ln_w + (size_t)i*Dd*Ii), (float4*)pWS, tN);
        tc_gemm<<<gD, 128, GEMM_SMEM_BYTES>>>(Dd, Ii, pGP, pWS, prB, ln_b + i*Dd, pXO, pY, pYT, nullptr, nullptr);
    }

    // logits = yt @ cvt(out_w)^T + out_b  -> [B,T,V]
    wcvt_kernel<<<(Vv * Dd / 4 + 255) / 256, 256>>>((const float4*)out_w, (float4*)pWS, Vv * Dd / 4);
    tc_gemm<<<gV, 128, GEMM_SMEM_BYTES>>>(Vv, Dd, pYT, pWS, nullptr, out_b, nullptr, out, nullptr, nullptr, nullptr);
}